// round 1
// baseline (speedup 1.0000x reference)
#include <cuda_runtime.h>
#include <cuda_bf16.h>
#include <math.h>
#include <stdint.h>

// ---------------- problem constants ----------------
#define BB 16
#define TT 512
#define DIN 1024
#define HH 256
#define NN 64
#define TOPK 8
#define NCLS 2
#define NCOEF 8
#define KBRIDGE (DIN * 9)      // 9216
#define KCONV (HH * 3)         // 768
#define MROWS (BB * TT)        // 8192
#define NROWS (BB * NN)        // 1024

// ---------------- scratch (__device__ globals; no allocation allowed) ---------
__device__ float g_f[(size_t)MROWS * KBRIDGE];      // 302 MB feature matrix
__device__ float g_wcat[HH * KBRIDGE];              // concat bridge weights
__device__ float g_h1[MROWS * HH];                  // bridge output [bt, c]
__device__ float g_col[(size_t)MROWS * KCONV];      // im2col buffer
__device__ float g_wc[HH * KCONV];                  // conv weight reordered
__device__ float g_y1[MROWS * HH];
__device__ float g_y2[MROWS * HH];
__device__ float g_hn[NROWS * HH];                  // node features [b*64+n, c]
__device__ float g_hw[NROWS * HH];
__device__ float g_wt[HH * HH];
__device__ float g_s[NROWS];
__device__ float g_d[NROWS];
__device__ unsigned long long g_adj[BB * NN];
__device__ float g_ln[NROWS * HH];

// ---------------- device math helpers ----------------
__device__ __forceinline__ float silu_f(float x) {
    return x * (1.f / (1.f + expf(-x)));
}
__device__ __forceinline__ float selu_f(float x) {
    const float a = 1.6732632423543772f, s = 1.0507009873554805f;
    return x > 0.f ? s * x : s * a * expm1f(x);
}
// efficient-KAN B-splines, grid_range=[-1,1], GRID=5, ORDER=3 -> 8 bases
__device__ __forceinline__ void bsplines8(float x, float* out) {
    const float h = 0.4f;
    float b[11];
#pragma unroll
    for (int j = 0; j < 11; j++) {
        float gj  = (float)(j - 3) * h - 1.0f;
        float gj1 = (float)(j - 2) * h - 1.0f;
        b[j] = (x >= gj && x < gj1) ? 1.f : 0.f;
    }
#pragma unroll
    for (int k = 1; k <= 3; k++) {
        float inv = 1.f / ((float)k * h);
#pragma unroll
        for (int j = 0; j < 11; j++) {
            if (j < 11 - k) {
                float gj   = (float)(j - 3) * h - 1.0f;
                float gjk1 = (float)(j + k - 2) * h - 1.0f;
                b[j] = (x - gj) * inv * b[j] + (gjk1 - x) * inv * b[j + 1];
            }
        }
    }
#pragma unroll
    for (int j = 0; j < 8; j++) out[j] = b[j];
}

// ---------------- feature / weight prep kernels ----------------
__global__ void bridge_features(const float* __restrict__ x) {
    size_t idx = (size_t)blockIdx.x * blockDim.x + threadIdx.x;
    if (idx >= (size_t)MROWS * DIN) return;
    size_t r = idx / DIN;
    int i = (int)(idx % DIN);
    float v = x[idx];
    float* fr = g_f + r * KBRIDGE;
    fr[i] = silu_f(v);
    float bs[8];
    bsplines8(v, bs);
#pragma unroll
    for (int c = 0; c < 8; c++) fr[(size_t)(c + 1) * DIN + i] = bs[c];
}

__global__ void build_wcat(const float* __restrict__ bw, const float* __restrict__ sw,
                           const float* __restrict__ sc) {
    int idx = blockIdx.x * blockDim.x + threadIdx.x;
    if (idx >= HH * DIN) return;
    int i = idx % DIN, o = idx / DIN;
    float* wr = g_wcat + (size_t)o * KBRIDGE;
    wr[i] = bw[idx];
    float scale = sc[idx];
#pragma unroll
    for (int c = 0; c < 8; c++) wr[(size_t)(c + 1) * DIN + i] = sw[(size_t)idx * 8 + c] * scale;
}

// im2col for conv1d k=3 pad=1: col[r, j*256+i], r = b*512+t
__global__ void im2col3(const float* __restrict__ src, float* __restrict__ col) {
    int idx = blockIdx.x * blockDim.x + threadIdx.x;
    if (idx >= MROWS * HH) return;
    int i = idx % HH;
    int r = idx / HH;
    int b = r / TT, t = r % TT;
#pragma unroll
    for (int j = 0; j < 3; j++) {
        int tt = t + j - 1;
        float v = (tt >= 0 && tt < TT) ? src[((size_t)b * TT + tt) * HH + i] : 0.f;
        col[(size_t)r * KCONV + j * HH + i] = v;
    }
}

__global__ void conv_w_reorder(const float* __restrict__ w, float* __restrict__ wc) {
    int idx = blockIdx.x * blockDim.x + threadIdx.x;
    if (idx >= HH * HH) return;
    int i = idx % HH, o = idx / HH;
#pragma unroll
    for (int j = 0; j < 3; j++)
        wc[(size_t)o * KCONV + j * HH + i] = w[((size_t)o * HH + i) * 3 + j];
}

__global__ void transpose256(const float* __restrict__ w, float* __restrict__ wt) {
    int idx = blockIdx.x * blockDim.x + threadIdx.x;
    if (idx >= HH * HH) return;
    int k = idx % HH, n = idx / HH;
    wt[idx] = w[(size_t)k * HH + n];   // wt[n*256+k] = W[k][n]
}

// ---------------- shared SGEMM: C[m,n] = sum_k A[m*K+k]*B[n*K+k] ----------------
#define BM 128
#define BN 64
#define BKK 16
template <int EPI>
__global__ __launch_bounds__(256) void sgemm_nt(const float* __restrict__ A,
                                                const float* __restrict__ B,
                                                float* __restrict__ C, int M, int N, int K,
                                                const float* __restrict__ bias) {
    __shared__ float As[BKK][BM];
    __shared__ float Bs[BKK][BN];
    int bm = blockIdx.y * BM;
    int bn = blockIdx.x * BN;
    int tid = threadIdx.x;
    int tx = tid % 16, ty = tid / 16;
    float acc[8][4];
#pragma unroll
    for (int i = 0; i < 8; i++)
#pragma unroll
        for (int j = 0; j < 4; j++) acc[i][j] = 0.f;

    int lrow = tid / 4;
    int lcol = (tid % 4) * 4;

    for (int k0 = 0; k0 < K; k0 += BKK) {
#pragma unroll
        for (int p = 0; p < 2; p++) {
            int r = lrow + p * 64;
            float4 v = *reinterpret_cast<const float4*>(&A[(size_t)(bm + r) * K + k0 + lcol]);
            As[lcol + 0][r] = v.x; As[lcol + 1][r] = v.y;
            As[lcol + 2][r] = v.z; As[lcol + 3][r] = v.w;
        }
        {
            float4 v = *reinterpret_cast<const float4*>(&B[(size_t)(bn + lrow) * K + k0 + lcol]);
            Bs[lcol + 0][lrow] = v.x; Bs[lcol + 1][lrow] = v.y;
            Bs[lcol + 2][lrow] = v.z; Bs[lcol + 3][lrow] = v.w;
        }
        __syncthreads();
#pragma unroll
        for (int kk = 0; kk < BKK; kk++) {
            float a[8], bvec[4];
#pragma unroll
            for (int i = 0; i < 8; i++) a[i] = As[kk][ty * 8 + i];
#pragma unroll
            for (int j = 0; j < 4; j++) bvec[j] = Bs[kk][tx * 4 + j];
#pragma unroll
            for (int i = 0; i < 8; i++)
#pragma unroll
                for (int j = 0; j < 4; j++) acc[i][j] = fmaf(a[i], bvec[j], acc[i][j]);
        }
        __syncthreads();
    }
#pragma unroll
    for (int i = 0; i < 8; i++) {
        int m = bm + ty * 8 + i;
#pragma unroll
        for (int j = 0; j < 4; j++) {
            int n = bn + tx * 4 + j;
            float v = acc[i][j];
            if (EPI == 1) v = selu_f(v + bias[n]);
            C[(size_t)m * N + n] = v;
        }
    }
}

// ---------------- pool + pos ----------------
__global__ void pool_pos(const float* __restrict__ y2, const float* __restrict__ pos) {
    int idx = blockIdx.x * blockDim.x + threadIdx.x;
    if (idx >= BB * NN * HH) return;
    int c = idx % HH;
    int n = (idx / HH) % NN;
    int b = idx / (HH * NN);
    float s = 0.f;
#pragma unroll
    for (int t = 0; t < 8; t++) s += y2[((size_t)b * TT + n * 8 + t) * HH + c];
    g_hn[((size_t)b * NN + n) * HH + c] = s * 0.125f + pos[(size_t)n * HH + c];
}

// ---------------- adjacency (bitmask per row) ----------------
__global__ void zero_adj() {
    int idx = blockIdx.x * blockDim.x + threadIdx.x;
    if (idx < BB * NN) g_adj[idx] = 0ull;
}

__global__ void adj_topk() {
    int b = blockIdx.x / NN, n = blockIdx.x % NN;
    __shared__ float sc[NN];
    int m = threadIdx.x;  // 64 threads
    const float* hb = g_hn + (size_t)b * NN * HH;
    float s = 0.f;
    for (int k = 0; k < HH; k++) s = fmaf(hb[(size_t)n * HH + k], hb[(size_t)m * HH + k], s);
    sc[m] = s;
    __syncthreads();
    if (m == 0) {
        unsigned long long mask = 1ull << n;  // self loop
        int sel[TOPK];
#pragma unroll 1
        for (int it = 0; it < TOPK; it++) {
            float best = -INFINITY; int bi = 0;
            for (int j = 0; j < NN; j++)
                if (sc[j] > best) { best = sc[j]; bi = j; }
            sel[it] = bi;
            sc[bi] = -INFINITY;
            mask |= 1ull << bi;
        }
        atomicOr(&g_adj[b * NN + n], mask);
        for (int it = 0; it < TOPK; it++)
            atomicOr(&g_adj[b * NN + sel[it]], 1ull << n);  // symmetrize (max == OR)
    }
}

// ---------------- GAT ----------------
__global__ void gat_sd(const float* __restrict__ asrc, const float* __restrict__ adst) {
    int row = blockIdx.x;
    __shared__ float r1[HH], r2[HH];
    int t = threadIdx.x;
    float v = g_hw[(size_t)row * HH + t];
    r1[t] = v * asrc[t];
    r2[t] = v * adst[t];
    __syncthreads();
    for (int st = 128; st > 0; st >>= 1) {
        if (t < st) { r1[t] += r1[t + st]; r2[t] += r2[t + st]; }
        __syncthreads();
    }
    if (t == 0) { g_s[row] = r1[0]; g_d[row] = r2[0]; }
}

__global__ void gat_attn() {
    int b = blockIdx.x / NN, n = blockIdx.x % NN;
    __shared__ float attn[NN];
    __shared__ float inv_s;
    int t = threadIdx.x;
    unsigned long long mask = g_adj[b * NN + n];
    if (t < NN) {
        float e;
        if ((mask >> t) & 1ull) {
            float z = g_s[b * NN + n] + g_d[b * NN + t];
            e = z >= 0.f ? z : 0.2f * z;   // leaky_relu(.,0.2)
        } else {
            e = -1e9f;
        }
        attn[t] = e;
    }
    __syncthreads();
    if (t == 0) {
        float mx = -INFINITY;
        for (int j = 0; j < NN; j++) mx = fmaxf(mx, attn[j]);
        float sum = 0.f;
        for (int j = 0; j < NN; j++) { float ex = expf(attn[j] - mx); attn[j] = ex; sum += ex; }
        inv_s = 1.f / sum;
    }
    __syncthreads();
    float inv = inv_s;
    float acc = 0.f;
    for (int m = 0; m < NN; m++)
        acc = fmaf(attn[m] * inv, g_hw[((size_t)b * NN + m) * HH + t], acc);
    float o = acc > 0.f ? acc : expm1f(acc);   // elu
    g_hn[((size_t)b * NN + n) * HH + t] += o;  // residual
}

// ---------------- layernorm ----------------
__global__ void layernorm_k(const float* __restrict__ g, const float* __restrict__ bt) {
    int row = blockIdx.x;
    __shared__ float red[HH];
    __shared__ float mu_s, is_s;
    int t = threadIdx.x;
    float v = g_hn[(size_t)row * HH + t];
    red[t] = v;
    __syncthreads();
    for (int st = 128; st > 0; st >>= 1) { if (t < st) red[t] += red[t + st]; __syncthreads(); }
    if (t == 0) mu_s = red[0] * (1.f / HH);
    __syncthreads();
    float mu = mu_s;
    float dv = v - mu;
    red[t] = dv * dv;
    __syncthreads();
    for (int st = 128; st > 0; st >>= 1) { if (t < st) red[t] += red[t + st]; __syncthreads(); }
    if (t == 0) is_s = rsqrtf(red[0] * (1.f / HH) + 1e-5f);
    __syncthreads();
    g_ln[(size_t)row * HH + t] = dv * is_s * g[t] + bt[t];
}

// ---------------- mean/max pooling -> emb written to d_out ----------------
__global__ void pool_emb(float* __restrict__ out) {
    int idx = blockIdx.x * blockDim.x + threadIdx.x;
    if (idx >= BB * HH) return;
    int b = idx / HH, c = idx % HH;
    float sm = 0.f, mx = -INFINITY;
    for (int n = 0; n < NN; n++) {
        float v = g_ln[((size_t)b * NN + n) * HH + c];
        sm += v;
        mx = fmaxf(mx, v);
    }
    out[BB * NCLS + (size_t)b * (2 * HH) + c] = sm * (1.f / NN);
    out[BB * NCLS + (size_t)b * (2 * HH) + HH + c] = mx;
}

// ---------------- classifier KAN ----------------
__global__ void cls_kan(const float* __restrict__ cbw, const float* __restrict__ csw,
                        const float* __restrict__ csc, float* __restrict__ out) {
    int b = blockIdx.x;
    int t = threadIdx.x;  // 256
    __shared__ float r0[256], r1[256];
    float a0 = 0.f, a1 = 0.f;
    const float* emb = out + BB * NCLS + (size_t)b * (2 * HH);
    for (int i = t; i < 2 * HH; i += 256) {
        float x = emb[i];
        float sil = silu_f(x);
        float bs[8];
        bsplines8(x, bs);
        float p0 = sil * cbw[i];
        float p1 = sil * cbw[2 * HH + i];
        float s0 = csc[i], s1 = csc[2 * HH + i];
#pragma unroll
        for (int c = 0; c < 8; c++) {
            p0 = fmaf(bs[c] * csw[(size_t)i * 8 + c], s0, p0);
            p1 = fmaf(bs[c] * csw[(size_t)(2 * HH + i) * 8 + c], s1, p1);
        }
        a0 += p0;
        a1 += p1;
    }
    r0[t] = a0; r1[t] = a1;
    __syncthreads();
    for (int st = 128; st > 0; st >>= 1) {
        if (t < st) { r0[t] += r0[t + st]; r1[t] += r1[t + st]; }
        __syncthreads();
    }
    if (t == 0) { out[b * NCLS + 0] = r0[0]; out[b * NCLS + 1] = r1[0]; }
}

// ---------------- host launch ----------------
extern "C" void kernel_launch(void* const* d_in, const int* in_sizes, int n_in,
                              void* d_out, int out_size) {
    const float* x      = (const float*)d_in[0];
    const float* bbw    = (const float*)d_in[1];
    const float* bsw    = (const float*)d_in[2];
    const float* bsc    = (const float*)d_in[3];
    const float* c1w    = (const float*)d_in[4];
    const float* c1b    = (const float*)d_in[5];
    const float* c2w    = (const float*)d_in[6];
    const float* c2b    = (const float*)d_in[7];
    const float* pos    = (const float*)d_in[8];
    const float* gatW   = (const float*)d_in[9];
    const float* asrc   = (const float*)d_in[10];
    const float* adst   = (const float*)d_in[11];
    const float* lng    = (const float*)d_in[12];
    const float* lnb    = (const float*)d_in[13];
    const float* cbw    = (const float*)d_in[14];
    const float* csw    = (const float*)d_in[15];
    const float* csc    = (const float*)d_in[16];
    float* out = (float*)d_out;

    float *pf, *pwcat, *ph1, *pcol, *pwc, *py1, *py2, *phn, *phw, *pwt;
    cudaGetSymbolAddress((void**)&pf, g_f);
    cudaGetSymbolAddress((void**)&pwcat, g_wcat);
    cudaGetSymbolAddress((void**)&ph1, g_h1);
    cudaGetSymbolAddress((void**)&pcol, g_col);
    cudaGetSymbolAddress((void**)&pwc, g_wc);
    cudaGetSymbolAddress((void**)&py1, g_y1);
    cudaGetSymbolAddress((void**)&py2, g_y2);
    cudaGetSymbolAddress((void**)&phn, g_hn);
    cudaGetSymbolAddress((void**)&phw, g_hw);
    cudaGetSymbolAddress((void**)&pwt, g_wt);

    const int TPB = 256;

    // KAN bridge
    bridge_features<<<(MROWS * DIN + TPB - 1) / TPB, TPB>>>(x);
    build_wcat<<<(HH * DIN + TPB - 1) / TPB, TPB>>>(bbw, bsw, bsc);
    dim3 gBig(HH / BN, MROWS / BM);
    sgemm_nt<0><<<gBig, 256>>>(pf, pwcat, ph1, MROWS, HH, KBRIDGE, nullptr);

    // conv1 + selu
    im2col3<<<(MROWS * HH + TPB - 1) / TPB, TPB>>>(ph1, pcol);
    conv_w_reorder<<<(HH * HH + TPB - 1) / TPB, TPB>>>(c1w, pwc);
    sgemm_nt<1><<<gBig, 256>>>(pcol, pwc, py1, MROWS, HH, KCONV, c1b);

    // conv2 + selu
    im2col3<<<(MROWS * HH + TPB - 1) / TPB, TPB>>>(py1, pcol);
    conv_w_reorder<<<(HH * HH + TPB - 1) / TPB, TPB>>>(c2w, pwc);
    sgemm_nt<1><<<gBig, 256>>>(pcol, pwc, py2, MROWS, HH, KCONV, c2b);

    // pool + pos
    pool_pos<<<(BB * NN * HH + TPB - 1) / TPB, TPB>>>(py2, pos);

    // adjacency
    zero_adj<<<(BB * NN + TPB - 1) / TPB, TPB>>>();
    adj_topk<<<BB * NN, NN>>>();

    // 2 residual GAT layers
    dim3 gSmall(HH / BN, NROWS / BM);
    for (int L = 0; L < 2; L++) {
        transpose256<<<(HH * HH + TPB - 1) / TPB, TPB>>>(gatW + (size_t)L * HH * HH, pwt);
        sgemm_nt<0><<<gSmall, 256>>>(phn, pwt, phw, NROWS, HH, HH, nullptr);
        gat_sd<<<NROWS, HH>>>(asrc + L * HH, adst + L * HH);
        gat_attn<<<NROWS, HH>>>();
    }

    // layernorm + pooling + classifier
    layernorm_k<<<NROWS, HH>>>(lng, lnb);
    pool_emb<<<(BB * HH + TPB - 1) / TPB, TPB>>>(out);
    cls_kan<<<BB, 256>>>(cbw, csw, csc, out);
}

// round 3
// speedup vs baseline: 2.4054x; 2.4054x over previous
#include <cuda_runtime.h>
#include <cuda_bf16.h>
#include <math.h>
#include <stdint.h>

typedef __nv_bfloat16 bf16;

// ---------------- problem constants ----------------
#define BB 16
#define TT 512
#define DIN 1024
#define HH 256
#define NN 64
#define TOPK 8
#define NCLS 2
#define KBRIDGE (DIN * 9)      // 9216
#define KCONV (HH * 3)         // 768
#define MROWS (BB * TT)        // 8192
#define NROWS (BB * NN)        // 1024

// ---------------- PTX helpers (sm_80-baseline features only) ----------------
__device__ __forceinline__ uint32_t smem_u32(const void* p) {
    uint32_t a;
    asm("{ .reg .u64 t; cvta.to.shared.u64 t, %1; cvt.u32.u64 %0, t; }" : "=r"(a) : "l"(p));
    return a;
}
#define CP_ASYNC16(dst, src) \
    asm volatile("cp.async.cg.shared.global [%0], [%1], 16;" :: "r"(dst), "l"(src) : "memory")
#define CP_COMMIT() asm volatile("cp.async.commit_group;" ::: "memory")
#define CP_WAIT(N)  asm volatile("cp.async.wait_group %0;" :: "n"(N) : "memory")
#define LDSM_X4(r0, r1, r2, r3, a) \
    asm volatile("ldmatrix.sync.aligned.m8n8.x4.shared.b16 {%0,%1,%2,%3}, [%4];" \
        : "=r"(r0), "=r"(r1), "=r"(r2), "=r"(r3) : "r"(a))
#define MMA_BF16(c, a0, a1, a2, a3, b0, b1) \
    asm volatile("mma.sync.aligned.m16n8k16.row.col.f32.bf16.bf16.f32 " \
        "{%0,%1,%2,%3}, {%4,%5,%6,%7}, {%8,%9}, {%0,%1,%2,%3};" \
        : "+f"((c)[0]), "+f"((c)[1]), "+f"((c)[2]), "+f"((c)[3]) \
        : "r"(a0), "r"(a1), "r"(a2), "r"(a3), "r"(b0), "r"(b1))

// ---------------- scratch (__device__ globals) ----------------
__device__ bf16 g_fh[(size_t)MROWS * KBRIDGE];
__device__ bf16 g_fl[(size_t)MROWS * KBRIDGE];
__device__ bf16 g_wh[HH * KBRIDGE];
__device__ bf16 g_wl[HH * KBRIDGE];
__device__ float g_h1[MROWS * HH];
__device__ bf16 g_colh[(size_t)MROWS * KCONV];
__device__ bf16 g_coll[(size_t)MROWS * KCONV];
__device__ bf16 g_wch[HH * KCONV];
__device__ bf16 g_wcl[HH * KCONV];
__device__ float g_y1[MROWS * HH];
__device__ float g_y2[MROWS * HH];
__device__ float g_hn[NROWS * HH];
__device__ bf16 g_hnh[NROWS * HH];
__device__ bf16 g_hnl[NROWS * HH];
__device__ bf16 g_wth[HH * HH];
__device__ bf16 g_wtl[HH * HH];
__device__ float g_hw[NROWS * HH];
__device__ float g_s[NROWS];
__device__ float g_d[NROWS];
__device__ unsigned long long g_adj[BB * NN];
__device__ float g_ln[NROWS * HH];

// ---------------- math helpers ----------------
__device__ __forceinline__ float silu_f(float x) { return x * (1.f / (1.f + expf(-x))); }
__device__ __forceinline__ float selu_f(float x) {
    const float a = 1.6732632423543772f, s = 1.0507009873554805f;
    return x > 0.f ? s * x : s * a * expm1f(x);
}
__device__ __forceinline__ void split_bf16(float v, bf16& h, bf16& l) {
    h = __float2bfloat16_rn(v);
    l = __float2bfloat16_rn(v - __bfloat162float(h));
}
__device__ __forceinline__ void bsplines8(float x, float* out) {
    const float h = 0.4f;
    float b[11];
#pragma unroll
    for (int j = 0; j < 11; j++) {
        float gj = (float)(j - 3) * h - 1.0f;
        float gj1 = (float)(j - 2) * h - 1.0f;
        b[j] = (x >= gj && x < gj1) ? 1.f : 0.f;
    }
#pragma unroll
    for (int k = 1; k <= 3; k++) {
        float inv = 1.f / ((float)k * h);
#pragma unroll
        for (int j = 0; j < 11; j++) {
            if (j < 11 - k) {
                float gj = (float)(j - 3) * h - 1.0f;
                float gjk1 = (float)(j + k - 2) * h - 1.0f;
                b[j] = (x - gj) * inv * b[j] + (gjk1 - x) * inv * b[j + 1];
            }
        }
    }
#pragma unroll
    for (int j = 0; j < 8; j++) out[j] = b[j];
}

// ---------------- prep kernels ----------------
__global__ void bridge_features_bf16(const float* __restrict__ x) {
    size_t idx = (size_t)blockIdx.x * blockDim.x + threadIdx.x;
    if (idx >= (size_t)MROWS * DIN) return;
    size_t r = idx / DIN;
    int i = (int)(idx % DIN);
    float v = x[idx];
    size_t base = r * KBRIDGE + i;
    bf16 h, l;
    split_bf16(silu_f(v), h, l);
    g_fh[base] = h; g_fl[base] = l;
    float bs[8];
    bsplines8(v, bs);
#pragma unroll
    for (int c = 0; c < 8; c++) {
        split_bf16(bs[c], h, l);
        size_t o = base + (size_t)(c + 1) * DIN;
        g_fh[o] = h; g_fl[o] = l;
    }
}

__global__ void build_wcat_bf16(const float* __restrict__ bw, const float* __restrict__ sw,
                                const float* __restrict__ sc) {
    int idx = blockIdx.x * blockDim.x + threadIdx.x;
    if (idx >= HH * DIN) return;
    int i = idx % DIN, o = idx / DIN;
    size_t base = (size_t)o * KBRIDGE + i;
    bf16 h, l;
    split_bf16(bw[idx], h, l);
    g_wh[base] = h; g_wl[base] = l;
    float scale = sc[idx];
#pragma unroll
    for (int c = 0; c < 8; c++) {
        split_bf16(sw[(size_t)idx * 8 + c] * scale, h, l);
        size_t p = base + (size_t)(c + 1) * DIN;
        g_wh[p] = h; g_wl[p] = l;
    }
}

__global__ void im2col3_bf16(const float* __restrict__ src) {
    int idx = blockIdx.x * blockDim.x + threadIdx.x;
    if (idx >= MROWS * HH) return;
    int i = idx % HH;
    int r = idx / HH;
    int b = r / TT, t = r % TT;
#pragma unroll
    for (int j = 0; j < 3; j++) {
        int tt = t + j - 1;
        float v = (tt >= 0 && tt < TT) ? src[((size_t)b * TT + tt) * HH + i] : 0.f;
        bf16 h, l;
        split_bf16(v, h, l);
        size_t o = (size_t)r * KCONV + j * HH + i;
        g_colh[o] = h; g_coll[o] = l;
    }
}

__global__ void conv_w_bf16(const float* __restrict__ w) {
    int idx = blockIdx.x * blockDim.x + threadIdx.x;
    if (idx >= HH * HH) return;
    int i = idx % HH, o = idx / HH;
#pragma unroll
    for (int j = 0; j < 3; j++) {
        bf16 h, l;
        split_bf16(w[((size_t)o * HH + i) * 3 + j], h, l);
        size_t p = (size_t)o * KCONV + j * HH + i;
        g_wch[p] = h; g_wcl[p] = l;
    }
}

__global__ void hn_to_bf16() {
    int idx = blockIdx.x * blockDim.x + threadIdx.x;
    if (idx >= NROWS * HH) return;
    bf16 h, l;
    split_bf16(g_hn[idx], h, l);
    g_hnh[idx] = h; g_hnl[idx] = l;
}

__global__ void gatwt_bf16(const float* __restrict__ w) {
    int idx = blockIdx.x * blockDim.x + threadIdx.x;
    if (idx >= HH * HH) return;
    int k = idx % HH, n = idx / HH;
    bf16 h, l;
    split_bf16(w[(size_t)k * HH + n], h, l);  // B[n,k] = W[k][n]
    g_wth[idx] = h; g_wtl[idx] = l;
}

// ---------------- mma.sync bf16-split GEMM ----------------
// C[m,n] = sum_k A[m,k]*B[n,k] with A,B each split hi/lo (3 products).
// CTA 256 threads, tile 128x128, BK=32, cp.async double buffer.
#define BKC 32
#define SPAD 40                        // padded row length (elements)
#define STG_BYTES (128 * SPAD * 2)     // 10240 per array per stage
#define ARR_BYTES (2 * STG_BYTES)      // 20480 (both stages)
#define GEMM_SMEM (4 * ARR_BYTES)      // 81920

template <int EPI>
__global__ __launch_bounds__(256, 1) void gemm_mma(
    const bf16* __restrict__ Ah, const bf16* __restrict__ Al,
    const bf16* __restrict__ Bh, const bf16* __restrict__ Bl,
    float* __restrict__ C, int K, const float* __restrict__ bias) {
    extern __shared__ char smem[];
    uint32_t s0 = smem_u32(smem);
    uint32_t sA[2] = {s0, s0 + ARR_BYTES};                       // Ah, Al
    uint32_t sB[2] = {s0 + 2 * ARR_BYTES, s0 + 3 * ARR_BYTES};   // Bh, Bl

    int tid = threadIdx.x, lane = tid & 31, wid = tid >> 5;
    int wm = wid & 3, wn = wid >> 2;
    int bm = blockIdx.x * 128, bn = blockIdx.y * 128;
    const int nc = K / BKC;

    const bf16* gA[2] = {Ah + (size_t)bm * K, Al + (size_t)bm * K};
    const bf16* gB[2] = {Bh + (size_t)bn * K, Bl + (size_t)bn * K};

    // ldmatrix per-lane byte offsets (within a stage)
    int aRow = wm * 32 + (lane & 15);
    int aCol = (lane >> 4) * 8;
    int bRow = wn * 64 + (lane & 7) + ((lane >> 4) << 3);
    int bCol = ((lane >> 3) & 1) * 8;

    float acc[2][8][4];
#pragma unroll
    for (int i = 0; i < 2; i++)
#pragma unroll
        for (int j = 0; j < 8; j++)
#pragma unroll
            for (int q = 0; q < 4; q++) acc[i][j][q] = 0.f;

    // stage loader: 512 x 16B chunks per array
    auto issue = [&](int stage, int k0) {
#pragma unroll
        for (int i = 0; i < 2; i++) {
            int q = i * 256 + tid;
            int r = q >> 2, c = q & 3;
            uint32_t d = (uint32_t)(stage * STG_BYTES + r * (SPAD * 2) + c * 16);
            size_t go = (size_t)r * K + k0 + c * 8;
            CP_ASYNC16(sA[0] + d, gA[0] + go);
            CP_ASYNC16(sA[1] + d, gA[1] + go);
            CP_ASYNC16(sB[0] + d, gB[0] + go);
            CP_ASYNC16(sB[1] + d, gB[1] + go);
        }
    };

    issue(0, 0);
    CP_COMMIT();

    for (int kc = 0; kc < nc; kc++) {
        if (kc + 1 < nc) {
            issue((kc + 1) & 1, (kc + 1) * BKC);
            CP_COMMIT();
            CP_WAIT(1);
        } else {
            CP_WAIT(0);
        }
        __syncthreads();
        uint32_t st = (uint32_t)((kc & 1) * STG_BYTES);
#pragma unroll
        for (int kk = 0; kk < 2; kk++) {
            uint32_t ah[2][4], al[2][4];
#pragma unroll
            for (int mt = 0; mt < 2; mt++) {
                uint32_t ao = st + (uint32_t)((aRow + mt * 16) * (SPAD * 2) + (aCol + kk * 16) * 2);
                LDSM_X4(ah[mt][0], ah[mt][1], ah[mt][2], ah[mt][3], sA[0] + ao);
                LDSM_X4(al[mt][0], al[mt][1], al[mt][2], al[mt][3], sA[1] + ao);
            }
#pragma unroll
            for (int nt2 = 0; nt2 < 4; nt2++) {
                uint32_t bo = st + (uint32_t)((bRow + nt2 * 16) * (SPAD * 2) + (bCol + kk * 16) * 2);
                uint32_t bh[4], bl[4];
                LDSM_X4(bh[0], bh[1], bh[2], bh[3], sB[0] + bo);
                LDSM_X4(bl[0], bl[1], bl[2], bl[3], sB[1] + bo);
#pragma unroll
                for (int mt = 0; mt < 2; mt++) {
                    int n0 = nt2 * 2, n1 = n0 + 1;
                    MMA_BF16(acc[mt][n0], ah[mt][0], ah[mt][1], ah[mt][2], ah[mt][3], bh[0], bh[1]);
                    MMA_BF16(acc[mt][n0], ah[mt][0], ah[mt][1], ah[mt][2], ah[mt][3], bl[0], bl[1]);
                    MMA_BF16(acc[mt][n0], al[mt][0], al[mt][1], al[mt][2], al[mt][3], bh[0], bh[1]);
                    MMA_BF16(acc[mt][n1], ah[mt][0], ah[mt][1], ah[mt][2], ah[mt][3], bh[2], bh[3]);
                    MMA_BF16(acc[mt][n1], ah[mt][0], ah[mt][1], ah[mt][2], ah[mt][3], bl[2], bl[3]);
                    MMA_BF16(acc[mt][n1], al[mt][0], al[mt][1], al[mt][2], al[mt][3], bh[2], bh[3]);
                }
            }
        }
        __syncthreads();
    }

    // epilogue
    int rbase = bm + wm * 32 + (lane >> 2);
    int cbase = bn + wn * 64 + (lane & 3) * 2;
#pragma unroll
    for (int mt = 0; mt < 2; mt++) {
#pragma unroll
        for (int nt = 0; nt < 8; nt++) {
            int r = rbase + mt * 16;
            int c = cbase + nt * 8;
            float v0 = acc[mt][nt][0], v1 = acc[mt][nt][1];
            float w0 = acc[mt][nt][2], w1 = acc[mt][nt][3];
            if (EPI == 1) {
                float b0 = bias[c], b1 = bias[c + 1];
                v0 = selu_f(v0 + b0); v1 = selu_f(v1 + b1);
                w0 = selu_f(w0 + b0); w1 = selu_f(w1 + b1);
            }
            *reinterpret_cast<float2*>(C + (size_t)r * 256 + c) = make_float2(v0, v1);
            *reinterpret_cast<float2*>(C + (size_t)(r + 8) * 256 + c) = make_float2(w0, w1);
        }
    }
}

// ---------------- pool + pos ----------------
__global__ void pool_pos(const float* __restrict__ y2, const float* __restrict__ pos) {
    int idx = blockIdx.x * blockDim.x + threadIdx.x;
    if (idx >= BB * NN * HH) return;
    int c = idx % HH;
    int n = (idx / HH) % NN;
    int b = idx / (HH * NN);
    float s = 0.f;
#pragma unroll
    for (int t = 0; t < 8; t++) s += y2[((size_t)b * TT + n * 8 + t) * HH + c];
    g_hn[((size_t)b * NN + n) * HH + c] = s * 0.125f + pos[(size_t)n * HH + c];
}

// ---------------- adjacency ----------------
__global__ void zero_adj() {
    int idx = blockIdx.x * blockDim.x + threadIdx.x;
    if (idx < BB * NN) g_adj[idx] = 0ull;
}

__global__ void adj_topk() {
    int b = blockIdx.x / NN, n = blockIdx.x % NN;
    __shared__ float sc[NN];
    int m = threadIdx.x;
    const float* hb = g_hn + (size_t)b * NN * HH;
    float s = 0.f;
    for (int k = 0; k < HH; k++) s = fmaf(hb[(size_t)n * HH + k], hb[(size_t)m * HH + k], s);
    sc[m] = s;
    __syncthreads();
    if (m == 0) {
        unsigned long long mask = 1ull << n;
        int sel[TOPK];
#pragma unroll 1
        for (int it = 0; it < TOPK; it++) {
            float best = -INFINITY; int bi = 0;
            for (int j = 0; j < NN; j++)
                if (sc[j] > best) { best = sc[j]; bi = j; }
            sel[it] = bi;
            sc[bi] = -INFINITY;
            mask |= 1ull << bi;
        }
        atomicOr(&g_adj[b * NN + n], mask);
        for (int it = 0; it < TOPK; it++)
            atomicOr(&g_adj[b * NN + sel[it]], 1ull << n);
    }
}

// ---------------- GAT ----------------
__global__ void gat_sd(const float* __restrict__ asrc, const float* __restrict__ adst) {
    int row = blockIdx.x;
    __shared__ float r1[HH], r2[HH];
    int t = threadIdx.x;
    float v = g_hw[(size_t)row * HH + t];
    r1[t] = v * asrc[t];
    r2[t] = v * adst[t];
    __syncthreads();
    for (int st = 128; st > 0; st >>= 1) {
        if (t < st) { r1[t] += r1[t + st]; r2[t] += r2[t + st]; }
        __syncthreads();
    }
    if (t == 0) { g_s[row] = r1[0]; g_d[row] = r2[0]; }
}

__global__ void gat_attn() {
    int b = blockIdx.x / NN, n = blockIdx.x % NN;
    __shared__ float attn[NN];
    __shared__ float inv_s;
    int t = threadIdx.x;
    unsigned long long mask = g_adj[b * NN + n];
    if (t < NN) {
        float e;
        if ((mask >> t) & 1ull) {
            float z = g_s[b * NN + n] + g_d[b * NN + t];
            e = z >= 0.f ? z : 0.2f * z;
        } else {
            e = -1e9f;
        }
        attn[t] = e;
    }
    __syncthreads();
    if (t == 0) {
        float mx = -INFINITY;
        for (int j = 0; j < NN; j++) mx = fmaxf(mx, attn[j]);
        float sum = 0.f;
        for (int j = 0; j < NN; j++) { float ex = expf(attn[j] - mx); attn[j] = ex; sum += ex; }
        inv_s = 1.f / sum;
    }
    __syncthreads();
    float inv = inv_s;
    float acc = 0.f;
    for (int m = 0; m < NN; m++)
        acc = fmaf(attn[m] * inv, g_hw[((size_t)b * NN + m) * HH + t], acc);
    float o = acc > 0.f ? acc : expm1f(acc);
    g_hn[((size_t)b * NN + n) * HH + t] += o;
}

// ---------------- layernorm ----------------
__global__ void layernorm_k(const float* __restrict__ g, const float* __restrict__ bt) {
    int row = blockIdx.x;
    __shared__ float red[HH];
    __shared__ float mu_s, is_s;
    int t = threadIdx.x;
    float v = g_hn[(size_t)row * HH + t];
    red[t] = v;
    __syncthreads();
    for (int st = 128; st > 0; st >>= 1) { if (t < st) red[t] += red[t + st]; __syncthreads(); }
    if (t == 0) mu_s = red[0] * (1.f / HH);
    __syncthreads();
    float mu = mu_s;
    float dv = v - mu;
    red[t] = dv * dv;
    __syncthreads();
    for (int st = 128; st > 0; st >>= 1) { if (t < st) red[t] += red[t + st]; __syncthreads(); }
    if (t == 0) is_s = rsqrtf(red[0] * (1.f / HH) + 1e-5f);
    __syncthreads();
    g_ln[(size_t)row * HH + t] = dv * is_s * g[t] + bt[t];
}

// ---------------- pooling + classifier ----------------
__global__ void pool_emb(float* __restrict__ out) {
    int idx = blockIdx.x * blockDim.x + threadIdx.x;
    if (idx >= BB * HH) return;
    int b = idx / HH, c = idx % HH;
    float sm = 0.f, mx = -INFINITY;
    for (int n = 0; n < NN; n++) {
        float v = g_ln[((size_t)b * NN + n) * HH + c];
        sm += v;
        mx = fmaxf(mx, v);
    }
    out[BB * NCLS + (size_t)b * (2 * HH) + c] = sm * (1.f / NN);
    out[BB * NCLS + (size_t)b * (2 * HH) + HH + c] = mx;
}

__global__ void cls_kan(const float* __restrict__ cbw, const float* __restrict__ csw,
                        const float* __restrict__ csc, float* __restrict__ out) {
    int b = blockIdx.x;
    int t = threadIdx.x;
    __shared__ float r0[256], r1[256];
    float a0 = 0.f, a1 = 0.f;
    const float* emb = out + BB * NCLS + (size_t)b * (2 * HH);
    for (int i = t; i < 2 * HH; i += 256) {
        float x = emb[i];
        float sil = silu_f(x);
        float bs[8];
        bsplines8(x, bs);
        float p0 = sil * cbw[i];
        float p1 = sil * cbw[2 * HH + i];
        float s0 = csc[i], s1 = csc[2 * HH + i];
#pragma unroll
        for (int c = 0; c < 8; c++) {
            p0 = fmaf(bs[c] * csw[(size_t)i * 8 + c], s0, p0);
            p1 = fmaf(bs[c] * csw[(size_t)(2 * HH + i) * 8 + c], s1, p1);
        }
        a0 += p0;
        a1 += p1;
    }
    r0[t] = a0; r1[t] = a1;
    __syncthreads();
    for (int st = 128; st > 0; st >>= 1) {
        if (t < st) { r0[t] += r0[t + st]; r1[t] += r1[t + st]; }
        __syncthreads();
    }
    if (t == 0) { out[b * NCLS + 0] = r0[0]; out[b * NCLS + 1] = r1[0]; }
}

// ---------------- host launch ----------------
extern "C" void kernel_launch(void* const* d_in, const int* in_sizes, int n_in,
                              void* d_out, int out_size) {
    const float* x    = (const float*)d_in[0];
    const float* bbw  = (const float*)d_in[1];
    const float* bsw  = (const float*)d_in[2];
    const float* bsc  = (const float*)d_in[3];
    const float* c1w  = (const float*)d_in[4];
    const float* c1b  = (const float*)d_in[5];
    const float* c2w  = (const float*)d_in[6];
    const float* c2b  = (const float*)d_in[7];
    const float* pos  = (const float*)d_in[8];
    const float* gatW = (const float*)d_in[9];
    const float* asrc = (const float*)d_in[10];
    const float* adst = (const float*)d_in[11];
    const float* lng  = (const float*)d_in[12];
    const float* lnb  = (const float*)d_in[13];
    const float* cbw  = (const float*)d_in[14];
    const float* csw  = (const float*)d_in[15];
    const float* csc  = (const float*)d_in[16];
    float* out = (float*)d_out;

    bf16 *pfh, *pfl, *pwh, *pwl, *pcolh, *pcoll, *pwch, *pwcl, *phnh, *phnl, *pwth, *pwtl;
    float *ph1, *py1, *py2, *phw;
    cudaGetSymbolAddress((void**)&pfh, g_fh);
    cudaGetSymbolAddress((void**)&pfl, g_fl);
    cudaGetSymbolAddress((void**)&pwh, g_wh);
    cudaGetSymbolAddress((void**)&pwl, g_wl);
    cudaGetSymbolAddress((void**)&pcolh, g_colh);
    cudaGetSymbolAddress((void**)&pcoll, g_coll);
    cudaGetSymbolAddress((void**)&pwch, g_wch);
    cudaGetSymbolAddress((void**)&pwcl, g_wcl);
    cudaGetSymbolAddress((void**)&phnh, g_hnh);
    cudaGetSymbolAddress((void**)&phnl, g_hnl);
    cudaGetSymbolAddress((void**)&pwth, g_wth);
    cudaGetSymbolAddress((void**)&pwtl, g_wtl);
    cudaGetSymbolAddress((void**)&ph1, g_h1);
    cudaGetSymbolAddress((void**)&py1, g_y1);
    cudaGetSymbolAddress((void**)&py2, g_y2);
    cudaGetSymbolAddress((void**)&phw, g_hw);

    cudaFuncSetAttribute(gemm_mma<0>, cudaFuncAttributeMaxDynamicSharedMemorySize, GEMM_SMEM);
    cudaFuncSetAttribute(gemm_mma<1>, cudaFuncAttributeMaxDynamicSharedMemorySize, GEMM_SMEM);

    const int TPB = 256;
    dim3 gBig(MROWS / 128, 2);
    dim3 gSmall(NROWS / 128, 2);

    // KAN bridge (tensor cores, bf16 split)
    bridge_features_bf16<<<(MROWS * DIN + TPB - 1) / TPB, TPB>>>(x);
    build_wcat_bf16<<<(HH * DIN + TPB - 1) / TPB, TPB>>>(bbw, bsw, bsc);
    gemm_mma<0><<<gBig, 256, GEMM_SMEM>>>(pfh, pfl, pwh, pwl, ph1, KBRIDGE, nullptr);

    // conv1 + selu
    im2col3_bf16<<<(MROWS * HH + TPB - 1) / TPB, TPB>>>(ph1);
    conv_w_bf16<<<(HH * HH + TPB - 1) / TPB, TPB>>>(c1w);
    gemm_mma<1><<<gBig, 256, GEMM_SMEM>>>(pcolh, pcoll, pwch, pwcl, py1, KCONV, c1b);

    // conv2 + selu
    im2col3_bf16<<<(MROWS * HH + TPB - 1) / TPB, TPB>>>(py1);
    conv_w_bf16<<<(HH * HH + TPB - 1) / TPB, TPB>>>(c2w);
    gemm_mma<1><<<gBig, 256, GEMM_SMEM>>>(pcolh, pcoll, pwch, pwcl, py2, KCONV, c2b);

    // pool + pos
    pool_pos<<<(BB * NN * HH + TPB - 1) / TPB, TPB>>>(py2, pos);

    // adjacency
    zero_adj<<<(BB * NN + TPB - 1) / TPB, TPB>>>();
    adj_topk<<<BB * NN, NN>>>();

    // 2 residual GAT layers
    for (int L = 0; L < 2; L++) {
        hn_to_bf16<<<(NROWS * HH + TPB - 1) / TPB, TPB>>>();
        gatwt_bf16<<<(HH * HH + TPB - 1) / TPB, TPB>>>(gatW + (size_t)L * HH * HH);
        gemm_mma<0><<<gSmall, 256, GEMM_SMEM>>>(phnh, phnl, pwth, pwtl, phw, HH, nullptr);
        gat_sd<<<NROWS, HH>>>(asrc + L * HH, adst + L * HH);
        gat_attn<<<NROWS, HH>>>();
    }

    // layernorm + pooling + classifier
    layernorm_k<<<NROWS, HH>>>(lng, lnb);
    pool_emb<<<(BB * HH + TPB - 1) / TPB, TPB>>>(out);
    cls_kan<<<BB, 256>>>(cbw, csw, csc, out);
}

// round 4
// speedup vs baseline: 2.6342x; 1.0951x over previous
#include <cuda_runtime.h>
#include <cuda_bf16.h>
#include <math.h>
#include <stdint.h>

typedef __nv_bfloat16 bf16;

// ---------------- problem constants ----------------
#define BB 16
#define TT 512
#define DIN 1024
#define HH 256
#define NN 64
#define TOPK 8
#define NCLS 2
#define KBRIDGE (DIN * 9)      // 9216
#define KCONV (HH * 3)         // 768
#define MROWS (BB * TT)        // 8192
#define NROWS (BB * NN)        // 1024

// ---------------- PTX helpers (sm_80-baseline features only) ----------------
__device__ __forceinline__ uint32_t smem_u32(const void* p) {
    uint32_t a;
    asm("{ .reg .u64 t; cvta.to.shared.u64 t, %1; cvt.u32.u64 %0, t; }" : "=r"(a) : "l"(p));
    return a;
}
#define CP_ASYNC16(dst, src) \
    asm volatile("cp.async.cg.shared.global [%0], [%1], 16;" :: "r"(dst), "l"(src) : "memory")
#define CP_COMMIT() asm volatile("cp.async.commit_group;" ::: "memory")
#define CP_WAIT(N)  asm volatile("cp.async.wait_group %0;" :: "n"(N) : "memory")
#define LDSM_X4(r0, r1, r2, r3, a) \
    asm volatile("ldmatrix.sync.aligned.m8n8.x4.shared.b16 {%0,%1,%2,%3}, [%4];" \
        : "=r"(r0), "=r"(r1), "=r"(r2), "=r"(r3) : "r"(a))
#define MMA_BF16(c, a0, a1, a2, a3, b0, b1) \
    asm volatile("mma.sync.aligned.m16n8k16.row.col.f32.bf16.bf16.f32 " \
        "{%0,%1,%2,%3}, {%4,%5,%6,%7}, {%8,%9}, {%0,%1,%2,%3};" \
        : "+f"((c)[0]), "+f"((c)[1]), "+f"((c)[2]), "+f"((c)[3]) \
        : "r"(a0), "r"(a1), "r"(a2), "r"(a3), "r"(b0), "r"(b1))

// ---------------- scratch (__device__ globals) ----------------
__device__ bf16 g_fh[(size_t)MROWS * KBRIDGE];
__device__ bf16 g_fl[(size_t)MROWS * KBRIDGE];
__device__ bf16 g_wh[HH * KBRIDGE];
__device__ bf16 g_wl[HH * KBRIDGE];
__device__ float g_h1[MROWS * HH];
__device__ bf16 g_colh[(size_t)MROWS * KCONV];
__device__ bf16 g_coll[(size_t)MROWS * KCONV];
__device__ bf16 g_wch[HH * KCONV];
__device__ bf16 g_wcl[HH * KCONV];
__device__ float g_y1[MROWS * HH];
__device__ float g_y2[MROWS * HH];
__device__ float g_hn[NROWS * HH];
__device__ bf16 g_hnh[NROWS * HH];
__device__ bf16 g_hnl[NROWS * HH];
__device__ bf16 g_wth[HH * HH];
__device__ bf16 g_wtl[HH * HH];
__device__ float g_hw[NROWS * HH];
__device__ float g_s[NROWS];
__device__ float g_d[NROWS];
__device__ unsigned long long g_adj[BB * NN];
__device__ float g_ln[NROWS * HH];

// ---------------- math helpers ----------------
__device__ __forceinline__ float silu_f(float x) { return x * (1.f / (1.f + expf(-x))); }
__device__ __forceinline__ float selu_f(float x) {
    const float a = 1.6732632423543772f, s = 1.0507009873554805f;
    return x > 0.f ? s * x : s * a * expm1f(x);
}
__device__ __forceinline__ void split_bf16(float v, bf16& h, bf16& l) {
    h = __float2bfloat16_rn(v);
    l = __float2bfloat16_rn(v - __bfloat162float(h));
}
union Pack4 { bf16 b[4]; uint2 u; };
__device__ __forceinline__ void split_store4(const float* v, bf16* ph, bf16* pl) {
    Pack4 H, L;
#pragma unroll
    for (int j = 0; j < 4; j++) split_bf16(v[j], H.b[j], L.b[j]);
    *reinterpret_cast<uint2*>(ph) = H.u;
    *reinterpret_cast<uint2*>(pl) = L.u;
}
__device__ __forceinline__ void bsplines8(float x, float* out) {
    const float h = 0.4f;
    float b[11];
#pragma unroll
    for (int j = 0; j < 11; j++) {
        float gj = (float)(j - 3) * h - 1.0f;
        float gj1 = (float)(j - 2) * h - 1.0f;
        b[j] = (x >= gj && x < gj1) ? 1.f : 0.f;
    }
#pragma unroll
    for (int k = 1; k <= 3; k++) {
        float inv = 1.f / ((float)k * h);
#pragma unroll
        for (int j = 0; j < 11; j++) {
            if (j < 11 - k) {
                float gj = (float)(j - 3) * h - 1.0f;
                float gjk1 = (float)(j + k - 2) * h - 1.0f;
                b[j] = (x - gj) * inv * b[j] + (gjk1 - x) * inv * b[j + 1];
            }
        }
    }
#pragma unroll
    for (int j = 0; j < 8; j++) out[j] = b[j];
}

// ---------------- prep kernels (vectorized, 4 inputs/thread) ----------------
__global__ void bridge_features_bf16(const float* __restrict__ x) {
    int idx = blockIdx.x * blockDim.x + threadIdx.x;
    if (idx >= MROWS * (DIN / 4)) return;
    int r = idx >> 8, i4 = idx & 255;
    float4 xv = *reinterpret_cast<const float4*>(x + (size_t)r * DIN + i4 * 4);
    float vv[4] = {xv.x, xv.y, xv.z, xv.w};
    float f[9][4];
#pragma unroll
    for (int j = 0; j < 4; j++) {
        f[0][j] = silu_f(vv[j]);
        float bs[8];
        bsplines8(vv[j], bs);
#pragma unroll
        for (int c = 0; c < 8; c++) f[c + 1][j] = bs[c];
    }
    size_t base = (size_t)r * KBRIDGE + i4 * 4;
#pragma unroll
    for (int g = 0; g < 9; g++)
        split_store4(f[g], g_fh + base + (size_t)g * DIN, g_fl + base + (size_t)g * DIN);
}

__global__ void build_wcat_bf16(const float* __restrict__ bw, const float* __restrict__ sw,
                                const float* __restrict__ sc) {
    int idx = blockIdx.x * blockDim.x + threadIdx.x;
    if (idx >= HH * (DIN / 4)) return;
    int o = idx >> 8, i4 = idx & 255;
    size_t wbase = (size_t)o * KBRIDGE + i4 * 4;
    float4 b4 = *reinterpret_cast<const float4*>(bw + (size_t)o * DIN + i4 * 4);
    float4 s4 = *reinterpret_cast<const float4*>(sc + (size_t)o * DIN + i4 * 4);
    float bb[4] = {b4.x, b4.y, b4.z, b4.w};
    float ss[4] = {s4.x, s4.y, s4.z, s4.w};
    split_store4(bb, g_wh + wbase, g_wl + wbase);
    // spline coefs: sw[(o*DIN+i)*8 + c] for 4 consecutive i
    float coef[4][8];
#pragma unroll
    for (int j = 0; j < 4; j++) {
        const float4* p = reinterpret_cast<const float4*>(sw + ((size_t)o * DIN + i4 * 4 + j) * 8);
        float4 c0 = p[0], c1 = p[1];
        coef[j][0] = c0.x * ss[j]; coef[j][1] = c0.y * ss[j];
        coef[j][2] = c0.z * ss[j]; coef[j][3] = c0.w * ss[j];
        coef[j][4] = c1.x * ss[j]; coef[j][5] = c1.y * ss[j];
        coef[j][6] = c1.z * ss[j]; coef[j][7] = c1.w * ss[j];
    }
#pragma unroll
    for (int c = 0; c < 8; c++) {
        float v[4] = {coef[0][c], coef[1][c], coef[2][c], coef[3][c]};
        split_store4(v, g_wh + wbase + (size_t)(c + 1) * DIN, g_wl + wbase + (size_t)(c + 1) * DIN);
    }
}

__global__ void im2col3_bf16(const float* __restrict__ src) {
    int idx = blockIdx.x * blockDim.x + threadIdx.x;
    if (idx >= MROWS * (HH / 4)) return;
    int i4 = idx & 63;
    int r = idx >> 6;
    int b = r / TT, t = r % TT;
#pragma unroll
    for (int j = 0; j < 3; j++) {
        int tt = t + j - 1;
        float v[4] = {0.f, 0.f, 0.f, 0.f};
        if (tt >= 0 && tt < TT) {
            float4 x4 = *reinterpret_cast<const float4*>(src + ((size_t)b * TT + tt) * HH + i4 * 4);
            v[0] = x4.x; v[1] = x4.y; v[2] = x4.z; v[3] = x4.w;
        }
        size_t o = (size_t)r * KCONV + j * HH + i4 * 4;
        split_store4(v, g_colh + o, g_coll + o);
    }
}

__global__ void conv_w_bf16(const float* __restrict__ w) {
    int idx = blockIdx.x * blockDim.x + threadIdx.x;
    if (idx >= HH * HH) return;
    int i = idx % HH, o = idx / HH;
#pragma unroll
    for (int j = 0; j < 3; j++) {
        bf16 h, l;
        split_bf16(w[((size_t)o * HH + i) * 3 + j], h, l);
        size_t p = (size_t)o * KCONV + j * HH + i;
        g_wch[p] = h; g_wcl[p] = l;
    }
}

__global__ void hn_to_bf16() {
    int idx = blockIdx.x * blockDim.x + threadIdx.x;
    if (idx >= NROWS * HH) return;
    bf16 h, l;
    split_bf16(g_hn[idx], h, l);
    g_hnh[idx] = h; g_hnl[idx] = l;
}

__global__ void gatwt_bf16(const float* __restrict__ w) {
    int idx = blockIdx.x * blockDim.x + threadIdx.x;
    if (idx >= HH * HH) return;
    int k = idx % HH, n = idx / HH;
    bf16 h, l;
    split_bf16(w[(size_t)k * HH + n], h, l);  // B[n,k] = W[k][n]
    g_wth[idx] = h; g_wtl[idx] = l;
}

// ---------------- mma.sync bf16-split GEMM ----------------
// C[m,n] = sum_k A[m,k]*B[n,k], A/B split hi/lo (3 products).
// CTA 256 threads (8 warps), tile 64(M) x 256(N full), BK=64, 2-stage cp.async.
#define BK 64
#define SROW 144                 // bytes per padded smem row (64*2 + 16)
#define A_STG (64 * SROW)        // 9216
#define B_STG (256 * SROW)       // 36864
#define GEMM_SMEM (4 * A_STG + 4 * B_STG)   // 184320

template <int EPI>
__global__ __launch_bounds__(256, 1) void gemm_mma(
    const bf16* __restrict__ Ah, const bf16* __restrict__ Al,
    const bf16* __restrict__ Bh, const bf16* __restrict__ Bl,
    float* __restrict__ C, int K, const float* __restrict__ bias) {
    extern __shared__ char smem[];
    uint32_t s0 = smem_u32(smem);
    uint32_t sAh = s0, sAl = s0 + 2 * A_STG;
    uint32_t sBh = s0 + 4 * A_STG, sBl = sBh + 2 * B_STG;

    int tid = threadIdx.x, lane = tid & 31, wid = tid >> 5;
    int wm = wid & 1, wn = wid >> 1;          // 2 x 4 warp grid
    int bm = blockIdx.x * 64;
    const int nc = K / BK;

    const bf16* gAh = Ah + (size_t)bm * K;
    const bf16* gAl = Al + (size_t)bm * K;

    int aRow = wm * 32 + (lane & 15);
    int aCol = (lane >> 4) * 8;
    int bRow = wn * 64 + (lane & 7) + ((lane >> 4) << 3);
    int bCol = ((lane >> 3) & 1) * 8;

    float acc[2][8][4];
#pragma unroll
    for (int i = 0; i < 2; i++)
#pragma unroll
        for (int j = 0; j < 8; j++)
#pragma unroll
            for (int q = 0; q < 4; q++) acc[i][j][q] = 0.f;

    auto issue = [&](int stage, int k0) {
        // A: 64 rows x 8 chunks = 512 chunks per array
#pragma unroll
        for (int i = 0; i < 2; i++) {
            int q = i * 256 + tid;
            int r = q >> 3, c = q & 7;
            uint32_t d = (uint32_t)(stage * A_STG + r * SROW + c * 16);
            size_t go = (size_t)r * K + k0 + c * 8;
            CP_ASYNC16(sAh + d, gAh + go);
            CP_ASYNC16(sAl + d, gAl + go);
        }
        // B: 256 rows x 8 chunks = 2048 chunks per array
#pragma unroll
        for (int i = 0; i < 8; i++) {
            int q = i * 256 + tid;
            int r = q >> 3, c = q & 7;
            uint32_t d = (uint32_t)(stage * B_STG + r * SROW + c * 16);
            size_t go = (size_t)r * K + k0 + c * 8;
            CP_ASYNC16(sBh + d, Bh + go);
            CP_ASYNC16(sBl + d, Bl + go);
        }
    };

    issue(0, 0);
    CP_COMMIT();

    for (int kc = 0; kc < nc; kc++) {
        if (kc + 1 < nc) {
            issue((kc + 1) & 1, (kc + 1) * BK);
            CP_COMMIT();
            CP_WAIT(1);
        } else {
            CP_WAIT(0);
        }
        __syncthreads();
        uint32_t stA = (uint32_t)((kc & 1) * A_STG);
        uint32_t stB = (uint32_t)((kc & 1) * B_STG);
#pragma unroll
        for (int kk = 0; kk < 4; kk++) {
            uint32_t ah[2][4], al[2][4];
#pragma unroll
            for (int mt = 0; mt < 2; mt++) {
                uint32_t ao = stA + (uint32_t)((aRow + mt * 16) * SROW + (aCol + kk * 16) * 2);
                LDSM_X4(ah[mt][0], ah[mt][1], ah[mt][2], ah[mt][3], sAh + ao);
                LDSM_X4(al[mt][0], al[mt][1], al[mt][2], al[mt][3], sAl + ao);
            }
#pragma unroll
            for (int nt2 = 0; nt2 < 4; nt2++) {
                uint32_t bo = stB + (uint32_t)((bRow + nt2 * 16) * SROW + (bCol + kk * 16) * 2);
                uint32_t bh[4], bl[4];
                LDSM_X4(bh[0], bh[1], bh[2], bh[3], sBh + bo);
                LDSM_X4(bl[0], bl[1], bl[2], bl[3], sBl + bo);
#pragma unroll
                for (int mt = 0; mt < 2; mt++) {
                    int n0 = nt2 * 2, n1 = n0 + 1;
                    MMA_BF16(acc[mt][n0], ah[mt][0], ah[mt][1], ah[mt][2], ah[mt][3], bh[0], bh[1]);
                    MMA_BF16(acc[mt][n0], ah[mt][0], ah[mt][1], ah[mt][2], ah[mt][3], bl[0], bl[1]);
                    MMA_BF16(acc[mt][n0], al[mt][0], al[mt][1], al[mt][2], al[mt][3], bh[0], bh[1]);
                    MMA_BF16(acc[mt][n1], ah[mt][0], ah[mt][1], ah[mt][2], ah[mt][3], bh[2], bh[3]);
                    MMA_BF16(acc[mt][n1], ah[mt][0], ah[mt][1], ah[mt][2], ah[mt][3], bl[2], bl[3]);
                    MMA_BF16(acc[mt][n1], al[mt][0], al[mt][1], al[mt][2], al[mt][3], bh[2], bh[3]);
                }
            }
        }
        __syncthreads();
    }

    // epilogue
    int rbase = bm + wm * 32 + (lane >> 2);
    int cbase = wn * 64 + (lane & 3) * 2;
#pragma unroll
    for (int mt = 0; mt < 2; mt++) {
#pragma unroll
        for (int nt = 0; nt < 8; nt++) {
            int r = rbase + mt * 16;
            int c = cbase + nt * 8;
            float v0 = acc[mt][nt][0], v1 = acc[mt][nt][1];
            float w0 = acc[mt][nt][2], w1 = acc[mt][nt][3];
            if (EPI == 1) {
                float b0 = bias[c], b1 = bias[c + 1];
                v0 = selu_f(v0 + b0); v1 = selu_f(v1 + b1);
                w0 = selu_f(w0 + b0); w1 = selu_f(w1 + b1);
            }
            *reinterpret_cast<float2*>(C + (size_t)r * 256 + c) = make_float2(v0, v1);
            *reinterpret_cast<float2*>(C + (size_t)(r + 8) * 256 + c) = make_float2(w0, w1);
        }
    }
}

// ---------------- pool + pos (+ zero adj) ----------------
__global__ void pool_pos(const float* __restrict__ y2, const float* __restrict__ pos) {
    int idx = blockIdx.x * blockDim.x + threadIdx.x;
    if (idx < BB * NN) g_adj[idx] = 0ull;
    if (idx >= BB * NN * HH) return;
    int c = idx % HH;
    int n = (idx / HH) % NN;
    int b = idx / (HH * NN);
    float s = 0.f;
#pragma unroll
    for (int t = 0; t < 8; t++) s += y2[((size_t)b * TT + n * 8 + t) * HH + c];
    g_hn[((size_t)b * NN + n) * HH + c] = s * 0.125f + pos[(size_t)n * HH + c];
}

// ---------------- adjacency ----------------
__global__ void adj_topk() {
    int b = blockIdx.x / NN, n = blockIdx.x % NN;
    __shared__ float sc[NN];
    int m = threadIdx.x;
    const float* hb = g_hn + (size_t)b * NN * HH;
    float s = 0.f;
    for (int k = 0; k < HH; k++) s = fmaf(hb[(size_t)n * HH + k], hb[(size_t)m * HH + k], s);
    sc[m] = s;
    __syncthreads();
    if (m == 0) {
        unsigned long long mask = 1ull << n;
        int sel[TOPK];
#pragma unroll 1
        for (int it = 0; it < TOPK; it++) {
            float best = -INFINITY; int bi = 0;
            for (int j = 0; j < NN; j++)
                if (sc[j] > best) { best = sc[j]; bi = j; }
            sel[it] = bi;
            sc[bi] = -INFINITY;
            mask |= 1ull << bi;
        }
        atomicOr(&g_adj[b * NN + n], mask);
        for (int it = 0; it < TOPK; it++)
            atomicOr(&g_adj[b * NN + sel[it]], 1ull << n);
    }
}

// ---------------- GAT ----------------
__global__ void gat_sd(const float* __restrict__ asrc, const float* __restrict__ adst) {
    int row = blockIdx.x;
    __shared__ float r1[HH], r2[HH];
    int t = threadIdx.x;
    float v = g_hw[(size_t)row * HH + t];
    r1[t] = v * asrc[t];
    r2[t] = v * adst[t];
    __syncthreads();
    for (int st = 128; st > 0; st >>= 1) {
        if (t < st) { r1[t] += r1[t + st]; r2[t] += r2[t + st]; }
        __syncthreads();
    }
    if (t == 0) { g_s[row] = r1[0]; g_d[row] = r2[0]; }
}

__global__ void gat_attn() {
    int b = blockIdx.x / NN, n = blockIdx.x % NN;
    __shared__ float attn[NN];
    __shared__ float inv_s;
    int t = threadIdx.x;
    unsigned long long mask = g_adj[b * NN + n];
    if (t < NN) {
        float e;
        if ((mask >> t) & 1ull) {
            float z = g_s[b * NN + n] + g_d[b * NN + t];
            e = z >= 0.f ? z : 0.2f * z;
        } else {
            e = -1e9f;
        }
        attn[t] = e;
    }
    __syncthreads();
    if (t == 0) {
        float mx = -INFINITY;
        for (int j = 0; j < NN; j++) mx = fmaxf(mx, attn[j]);
        float sum = 0.f;
        for (int j = 0; j < NN; j++) { float ex = expf(attn[j] - mx); attn[j] = ex; sum += ex; }
        inv_s = 1.f / sum;
    }
    __syncthreads();
    float inv = inv_s;
    float acc = 0.f;
    for (int m = 0; m < NN; m++)
        acc = fmaf(attn[m] * inv, g_hw[((size_t)b * NN + m) * HH + t], acc);
    float o = acc > 0.f ? acc : expm1f(acc);
    g_hn[((size_t)b * NN + n) * HH + t] += o;
}

// ---------------- layernorm ----------------
__global__ void layernorm_k(const float* __restrict__ g, const float* __restrict__ bt) {
    int row = blockIdx.x;
    __shared__ float red[HH];
    __shared__ float mu_s, is_s;
    int t = threadIdx.x;
    float v = g_hn[(size_t)row * HH + t];
    red[t] = v;
    __syncthreads();
    for (int st = 128; st > 0; st >>= 1) { if (t < st) red[t] += red[t + st]; __syncthreads(); }
    if (t == 0) mu_s = red[0] * (1.f / HH);
    __syncthreads();
    float mu = mu_s;
    float dv = v - mu;
    red[t] = dv * dv;
    __syncthreads();
    for (int st = 128; st > 0; st >>= 1) { if (t < st) red[t] += red[t + st]; __syncthreads(); }
    if (t == 0) is_s = rsqrtf(red[0] * (1.f / HH) + 1e-5f);
    __syncthreads();
    g_ln[(size_t)row * HH + t] = dv * is_s * g[t] + bt[t];
}

// ---------------- pooling + classifier ----------------
__global__ void pool_emb(float* __restrict__ out) {
    int idx = blockIdx.x * blockDim.x + threadIdx.x;
    if (idx >= BB * HH) return;
    int b = idx / HH, c = idx % HH;
    float sm = 0.f, mx = -INFINITY;
    for (int n = 0; n < NN; n++) {
        float v = g_ln[((size_t)b * NN + n) * HH + c];
        sm += v;
        mx = fmaxf(mx, v);
    }
    out[BB * NCLS + (size_t)b * (2 * HH) + c] = sm * (1.f / NN);
    out[BB * NCLS + (size_t)b * (2 * HH) + HH + c] = mx;
}

__global__ void cls_kan(const float* __restrict__ cbw, const float* __restrict__ csw,
                        const float* __restrict__ csc, float* __restrict__ out) {
    int b = blockIdx.x;
    int t = threadIdx.x;
    __shared__ float r0[256], r1[256];
    float a0 = 0.f, a1 = 0.f;
    const float* emb = out + BB * NCLS + (size_t)b * (2 * HH);
    for (int i = t; i < 2 * HH; i += 256) {
        float x = emb[i];
        float sil = silu_f(x);
        float bs[8];
        bsplines8(x, bs);
        float p0 = sil * cbw[i];
        float p1 = sil * cbw[2 * HH + i];
        float s0 = csc[i], s1 = csc[2 * HH + i];
#pragma unroll
        for (int c = 0; c < 8; c++) {
            p0 = fmaf(bs[c] * csw[(size_t)i * 8 + c], s0, p0);
            p1 = fmaf(bs[c] * csw[(size_t)(2 * HH + i) * 8 + c], s1, p1);
        }
        a0 += p0;
        a1 += p1;
    }
    r0[t] = a0; r1[t] = a1;
    __syncthreads();
    for (int st = 128; st > 0; st >>= 1) {
        if (t < st) { r0[t] += r0[t + st]; r1[t] += r1[t + st]; }
        __syncthreads();
    }
    if (t == 0) { out[b * NCLS + 0] = r0[0]; out[b * NCLS + 1] = r1[0]; }
}

// ---------------- host launch ----------------
extern "C" void kernel_launch(void* const* d_in, const int* in_sizes, int n_in,
                              void* d_out, int out_size) {
    const float* x    = (const float*)d_in[0];
    const float* bbw  = (const float*)d_in[1];
    const float* bsw  = (const float*)d_in[2];
    const float* bsc  = (const float*)d_in[3];
    const float* c1w  = (const float*)d_in[4];
    const float* c1b  = (const float*)d_in[5];
    const float* c2w  = (const float*)d_in[6];
    const float* c2b  = (const float*)d_in[7];
    const float* pos  = (const float*)d_in[8];
    const float* gatW = (const float*)d_in[9];
    const float* asrc = (const float*)d_in[10];
    const float* adst = (const float*)d_in[11];
    const float* lng  = (const float*)d_in[12];
    const float* lnb  = (const float*)d_in[13];
    const float* cbw  = (const float*)d_in[14];
    const float* csw  = (const float*)d_in[15];
    const float* csc  = (const float*)d_in[16];
    float* out = (float*)d_out;

    bf16 *pfh, *pfl, *pwh, *pwl, *pcolh, *pcoll, *pwch, *pwcl, *phnh, *phnl, *pwth, *pwtl;
    float *ph1, *py1, *py2, *phw;
    cudaGetSymbolAddress((void**)&pfh, g_fh);
    cudaGetSymbolAddress((void**)&pfl, g_fl);
    cudaGetSymbolAddress((void**)&pwh, g_wh);
    cudaGetSymbolAddress((void**)&pwl, g_wl);
    cudaGetSymbolAddress((void**)&pcolh, g_colh);
    cudaGetSymbolAddress((void**)&pcoll, g_coll);
    cudaGetSymbolAddress((void**)&pwch, g_wch);
    cudaGetSymbolAddress((void**)&pwcl, g_wcl);
    cudaGetSymbolAddress((void**)&phnh, g_hnh);
    cudaGetSymbolAddress((void**)&phnl, g_hnl);
    cudaGetSymbolAddress((void**)&pwth, g_wth);
    cudaGetSymbolAddress((void**)&pwtl, g_wtl);
    cudaGetSymbolAddress((void**)&ph1, g_h1);
    cudaGetSymbolAddress((void**)&py1, g_y1);
    cudaGetSymbolAddress((void**)&py2, g_y2);
    cudaGetSymbolAddress((void**)&phw, g_hw);

    cudaFuncSetAttribute(gemm_mma<0>, cudaFuncAttributeMaxDynamicSharedMemorySize, GEMM_SMEM);
    cudaFuncSetAttribute(gemm_mma<1>, cudaFuncAttributeMaxDynamicSharedMemorySize, GEMM_SMEM);

    const int TPB = 256;

    // KAN bridge (tensor cores, bf16 split)
    bridge_features_bf16<<<MROWS * (DIN / 4) / TPB, TPB>>>(x);
    build_wcat_bf16<<<HH * (DIN / 4) / TPB, TPB>>>(bbw, bsw, bsc);
    gemm_mma<0><<<MROWS / 64, 256, GEMM_SMEM>>>(pfh, pfl, pwh, pwl, ph1, KBRIDGE, nullptr);

    // conv1 + selu
    im2col3_bf16<<<MROWS * (HH / 4) / TPB, TPB>>>(ph1);
    conv_w_bf16<<<(HH * HH + TPB - 1) / TPB, TPB>>>(c1w);
    gemm_mma<1><<<MROWS / 64, 256, GEMM_SMEM>>>(pcolh, pcoll, pwch, pwcl, py1, KCONV, c1b);

    // conv2 + selu
    im2col3_bf16<<<MROWS * (HH / 4) / TPB, TPB>>>(py1);
    conv_w_bf16<<<(HH * HH + TPB - 1) / TPB, TPB>>>(c2w);
    gemm_mma<1><<<MROWS / 64, 256, GEMM_SMEM>>>(pcolh, pcoll, pwch, pwcl, py2, KCONV, c2b);

    // pool + pos (+ adj zero)
    pool_pos<<<(BB * NN * HH + TPB - 1) / TPB, TPB>>>(py2, pos);

    // adjacency
    adj_topk<<<BB * NN, NN>>>();

    // 2 residual GAT layers
    for (int L = 0; L < 2; L++) {
        hn_to_bf16<<<(NROWS * HH + TPB - 1) / TPB, TPB>>>();
        gatwt_bf16<<<(HH * HH + TPB - 1) / TPB, TPB>>>(gatW + (size_t)L * HH * HH);
        gemm_mma<0><<<NROWS / 64, 256, GEMM_SMEM>>>(phnh, phnl, pwth, pwtl, phw, HH, nullptr);
        gat_sd<<<NROWS, HH>>>(asrc + L * HH, adst + L * HH);
        gat_attn<<<NROWS, HH>>>();
    }

    // layernorm + pooling + classifier
    layernorm_k<<<NROWS, HH>>>(lng, lnb);
    pool_emb<<<(BB * HH + TPB - 1) / TPB, TPB>>>(out);
    cls_kan<<<BB, 256>>>(cbw, csw, csc, out);
}